// round 13
// baseline (speedup 1.0000x reference)
#include <cuda_runtime.h>
#include <cuda_fp16.h>
#include <math.h>

#define MIN_ROUGHNESS 0.08f
#define MAX_ROUGHNESS 0.5f
#define N_MIPS 6

// Quad-record arrays (one uint4 per texel position; record at (x,y) holds the
// full 2x2 bilinear footprint {(x,y),(x+1,y),(x,y+1),(x+1,y+1)}, neighbors
// clamped at face edges). Spec/diffuse texels are RGB9E5 (4B each); FG is fp16.
#define PAIR_TOTAL_TEXELS 523776   // mips 1..5
#define DIFF_TEXELS 1536
#define FG_TEXELS 65536

__constant__ int PAIR_OFF[6] = {0, 393216, 491520, 516096, 522240, 523776};

__device__ uint4 g_specq[PAIR_TOTAL_TEXELS];  // rgb9e5 quads (8.4 MB)
__device__ uint4 g_diffq[DIFF_TEXELS];        // rgb9e5 quads (24 KB)
__device__ uint4 g_fgq[FG_TEXELS];            // fp16 (fg0,fg1) quads (1 MB)

struct SpecTable {
    const float* p[N_MIPS];
};

struct float3x { float x, y, z; };

// ---------------------------------------------------------------------------
// RGB9E5 shared-exponent encode/decode
// ---------------------------------------------------------------------------
__device__ __forceinline__ unsigned int enc_rgb9e5(float r, float g, float b) {
    r = fmaxf(r, 0.0f); g = fmaxf(g, 0.0f); b = fmaxf(b, 0.0f);
    float maxc = fmaxf(r, fmaxf(g, b));
    if (maxc < 1e-12f) return 0u;
    int e;
    frexpf(maxc, &e);              // maxc = f * 2^e, f in [0.5, 1)
    if (e < -15) e = -15;
    if (e > 15)  e = 15;
    float scale = exp2f((float)(9 - e));
    int mr = __float2int_rn(r * scale); if (mr > 511) mr = 511;
    int mg = __float2int_rn(g * scale); if (mg > 511) mg = 511;
    int mb = __float2int_rn(b * scale); if (mb > 511) mb = 511;
    return (unsigned int)mr | ((unsigned int)mg << 9) |
           ((unsigned int)mb << 18) | ((unsigned int)(e + 16) << 27);
}

__device__ __forceinline__ float3x dec_rgb9e5(unsigned int v) {
    int ef = (int)(v >> 27);                       // e + 16
    float scale = __int_as_float((ef - 16 - 9 + 127) << 23);
    float3x c;
    c.x = (float)(v & 0x1FFu) * scale;
    c.y = (float)((v >> 9) & 0x1FFu) * scale;
    c.z = (float)((v >> 18) & 0x1FFu) * scale;
    return c;
}

// ---------------------------------------------------------------------------
// Repack pass: one record per thread.
// ---------------------------------------------------------------------------
__device__ __forceinline__ unsigned int enc_texel(const float* __restrict__ t) {
    return enc_rgb9e5(t[0], t[1], t[2]);
}

__global__ void __launch_bounds__(256)
repack_kernel(SpecTable specs, const float* __restrict__ diffuse,
              const float* __restrict__ fg_lut) {
    const int NS = PAIR_TOTAL_TEXELS;
    const int ND = NS + DIFF_TEXELS;
    const int NF = ND + FG_TEXELS;
    int r = blockIdx.x * blockDim.x + threadIdx.x;
    if (r >= NF) return;

    if (r < NS) {
        int lvl = 1;
        if (r >= 393216) lvl = 2;
        if (r >= 491520) lvl = 3;
        if (r >= 516096) lvl = 4;
        if (r >= 522240) lvl = 5;
        int local = r - PAIR_OFF[lvl - 1];
        int lr = 9 - lvl;                 // log2(R)
        int R = 1 << lr;
        int x = local & (R - 1);
        int y = (local >> lr) & (R - 1);
        int face = local >> (2 * lr);
        int x1 = (x + 1 < R) ? (x + 1) : x;
        int y1 = (y + 1 < R) ? (y + 1) : y;
        const float* base = specs.p[lvl] + (size_t)face * R * R * 3;
        uint4 o;
        o.x = enc_texel(base + (y  * R + x ) * 3);
        o.y = enc_texel(base + (y  * R + x1) * 3);
        o.z = enc_texel(base + (y1 * R + x ) * 3);
        o.w = enc_texel(base + (y1 * R + x1) * 3);
        g_specq[r] = o;
    } else if (r < ND) {
        int local = r - NS;
        const int R = 16;
        int x = local & 15;
        int y = (local >> 4) & 15;
        int face = local >> 8;
        int x1 = (x + 1 < R) ? (x + 1) : x;
        int y1 = (y + 1 < R) ? (y + 1) : y;
        const float* base = diffuse + (size_t)face * 256 * 3;
        uint4 o;
        o.x = enc_texel(base + (y  * R + x ) * 3);
        o.y = enc_texel(base + (y  * R + x1) * 3);
        o.z = enc_texel(base + (y1 * R + x ) * 3);
        o.w = enc_texel(base + (y1 * R + x1) * 3);
        g_diffq[local] = o;   // FIXED: was g_diffq[r]
    } else {
        int local = r - ND;
        int x = local & 255;
        int y = local >> 8;
        int x1 = (x + 1 < 256) ? (x + 1) : x;
        int y1 = (y + 1 < 256) ? (y + 1) : y;
        const float2* fg = (const float2*)fg_lut;
        float2 c00 = __ldg(fg + y  * 256 + x);
        float2 c01 = __ldg(fg + y  * 256 + x1);
        float2 c10 = __ldg(fg + y1 * 256 + x);
        float2 c11 = __ldg(fg + y1 * 256 + x1);
        __half2 h00 = __floats2half2_rn(c00.x, c00.y);
        __half2 h01 = __floats2half2_rn(c01.x, c01.y);
        __half2 h10 = __floats2half2_rn(c10.x, c10.y);
        __half2 h11 = __floats2half2_rn(c11.x, c11.y);
        uint4 o;
        o.x = *reinterpret_cast<unsigned int*>(&h00);
        o.y = *reinterpret_cast<unsigned int*>(&h01);
        o.z = *reinterpret_cast<unsigned int*>(&h10);
        o.w = *reinterpret_cast<unsigned int*>(&h11);
        g_fgq[local] = o;
    }
}

// ---------------------------------------------------------------------------
// Main shading kernel
// ---------------------------------------------------------------------------
__device__ __forceinline__ void cube_face_uv(float x, float y, float z,
                                             int& face, float& u, float& v) {
    float ax = fabsf(x), ay = fabsf(y), az = fabsf(z);
    bool is_x = (ax >= ay) && (ax >= az);
    bool is_y = (!is_x) && (ay >= az);
    face = is_x ? (x >= 0.0f ? 0 : 1)
                : (is_y ? (y >= 0.0f ? 2 : 3)
                        : (z >= 0.0f ? 4 : 5));
    float ma = fmaxf(is_x ? ax : (is_y ? ay : az), 1e-20f);
    float un = (face == 0) ? -z : (face == 1) ? z : (face == 5) ? -x : x;
    float vn = (face == 2) ? z : (face == 3) ? -z : -y;
    float inv = __fdividef(1.0f, ma);
    u = un * inv;
    v = vn * inv;
}

// Quad-record bilinear: ONE LDG.128 per sample.
__device__ __forceinline__ float3x cube_bilinear_quad(const uint4* __restrict__ tex,
                                                      int R, int face,
                                                      float u, float v) {
    float Rf = (float)R;
    float tu = fmaf(u, 0.5f * Rf, 0.5f * Rf - 0.5f);
    float tv = fmaf(v, 0.5f * Rf, 0.5f * Rf - 0.5f);
    float x0f = floorf(tu);
    float y0f = floorf(tv);
    float fx = tu - x0f;
    if (x0f < 0.0f) fx = 0.0f;
    float fy = tv - y0f;
    if (y0f < 0.0f) fy = 0.0f;
    int x0 = (int)fminf(fmaxf(x0f, 0.0f), Rf - 1.0f);
    int y0 = (int)fminf(fmaxf(y0f, 0.0f), Rf - 1.0f);

    uint4 e = __ldg(tex + face * R * R + y0 * R + x0);
    float3x c00 = dec_rgb9e5(e.x);
    float3x c01 = dec_rgb9e5(e.y);
    float3x c10 = dec_rgb9e5(e.z);
    float3x c11 = dec_rgb9e5(e.w);

    float r0 = c00.x + fx * (c01.x - c00.x);
    float g0 = c00.y + fx * (c01.y - c00.y);
    float b0 = c00.z + fx * (c01.z - c00.z);
    float r1 = c10.x + fx * (c11.x - c10.x);
    float g1 = c10.y + fx * (c11.y - c10.y);
    float b1 = c10.z + fx * (c11.z - c10.z);

    float3x r;
    r.x = r0 + fy * (r1 - r0);
    r.y = g0 + fy * (g1 - g0);
    r.z = b0 + fy * (b1 - b0);
    return r;
}

// Raw fp32 RGB bilinear on the original mip-0 buffer (exact).
__device__ __forceinline__ float3x cube_bilinear_raw(const float* __restrict__ tex,
                                                     int face, float u, float v) {
    const float Rf = 512.0f;
    float tu = fmaf(u, 0.5f * Rf, 0.5f * Rf - 0.5f);
    float tv = fmaf(v, 0.5f * Rf, 0.5f * Rf - 0.5f);
    float x0f = floorf(tu);
    float y0f = floorf(tv);
    float fx = tu - x0f;
    float fy = tv - y0f;
    int x0 = (int)fminf(fmaxf(x0f, 0.0f), Rf - 1.0f);
    int x1 = (int)fminf(fmaxf(x0f + 1.0f, 0.0f), Rf - 1.0f);
    int y0 = (int)fminf(fmaxf(y0f, 0.0f), Rf - 1.0f);
    int y1 = (int)fminf(fmaxf(y0f + 1.0f, 0.0f), Rf - 1.0f);

    int baseF = face * 512 * 512;
    int i00 = (baseF + y0 * 512 + x0) * 3;
    int i01 = (baseF + y0 * 512 + x1) * 3;
    int i10 = (baseF + y1 * 512 + x0) * 3;
    int i11 = (baseF + y1 * 512 + x1) * 3;

    float w00 = (1.0f - fx) * (1.0f - fy);
    float w01 = fx * (1.0f - fy);
    float w10 = (1.0f - fx) * fy;
    float w11 = fx * fy;

    float3x r;
    r.x = __ldg(tex + i00 + 0) * w00 + __ldg(tex + i01 + 0) * w01 +
          __ldg(tex + i10 + 0) * w10 + __ldg(tex + i11 + 0) * w11;
    r.y = __ldg(tex + i00 + 1) * w00 + __ldg(tex + i01 + 1) * w01 +
          __ldg(tex + i10 + 1) * w10 + __ldg(tex + i11 + 1) * w11;
    r.z = __ldg(tex + i00 + 2) * w00 + __ldg(tex + i01 + 2) * w01 +
          __ldg(tex + i10 + 2) * w10 + __ldg(tex + i11 + 2) * w11;
    return r;
}

__device__ __forceinline__ float linear2srgb(float x) {
    float l = __log2f(x);
    float y = l * (1.0f / 2.4f);
    float fl = floorf(y);
    float t = y - fl;
    float p = fmaf(t,
              fmaf(t,
              fmaf(t,
              fmaf(t,
              fmaf(t, 0.0013333558f, 0.0096181291f),
                       0.0555041087f),
                       0.2402265070f),
                       0.6931471806f),
                       1.0f);
    int e = (int)fl;
    float r = __int_as_float(__float_as_int(p) + (e << 23));
    float hi = fmaf(1.055f, r, -0.055f);
    return (x > 0.0031308f) ? hi : 12.92f * x;
}

__global__ void __launch_bounds__(256, 6)
envlight_kernel1(const float* __restrict__ gb_pos,
                 const float* __restrict__ gb_normal,
                 const float* __restrict__ basecolor,
                 const float* __restrict__ metallic,
                 const float* __restrict__ roughness,
                 const float* __restrict__ view_pos,
                 const float* __restrict__ spec0,
                 float* __restrict__ out,
                 int n) {
    int i = blockIdx.x * blockDim.x + threadIdx.x;
    if (i >= n) return;

    float vx = __ldg(view_pos + 0);
    float vy = __ldg(view_pos + 1);
    float vz = __ldg(view_pos + 2);

    float px = __ldcs(gb_pos + i * 3 + 0);
    float py = __ldcs(gb_pos + i * 3 + 1);
    float pz = __ldcs(gb_pos + i * 3 + 2);
    float nx = __ldcs(gb_normal + i * 3 + 0);
    float ny = __ldcs(gb_normal + i * 3 + 1);
    float nz = __ldcs(gb_normal + i * 3 + 2);
    float bcx = __ldcs(basecolor + i * 3 + 0);
    float bcy = __ldcs(basecolor + i * 3 + 1);
    float bcz = __ldcs(basecolor + i * 3 + 2);
    float met = __ldcs(metallic + i);
    float rough = __ldcs(roughness + i);

    // wo left unnormalized; only NdotV needs the normalization factor.
    float wx = vx - px, wy = vy - py, wz = vz - pz;
    float wlen2 = fmaxf(wx * wx + wy * wy + wz * wz, 1e-20f);
    float winv = rsqrtf(wlen2);

    float om = 1.0f - met;
    float dax = om * bcx, day = om * bcy, daz = om * bcz;
    float sax = 0.04f * om + met * bcx;
    float say = 0.04f * om + met * bcy;
    float saz = 0.04f * om + met * bcz;

    float d_un = wx * nx + wy * ny + wz * nz;
    float rx = 2.0f * d_un * nx - wx;
    float ry = 2.0f * d_un * ny - wy;
    float rz = 2.0f * d_un * nz - wz;

    // ambient from diffuse cubemap (one quad load)
    int dface; float du, dv;
    cube_face_uv(nx, ny, nz, dface, du, dv);
    float3x ambient = cube_bilinear_quad(g_diffq, 16, dface, du, dv);

    float dlx = ambient.x * dax;
    float dly = ambient.y * day;
    float dlz = ambient.z * daz;

    // FG LUT: one LDG.128 quad record (fp16)
    float NdotV = fmaxf(d_un * winv, 0.0001f);
    float fg0, fg1;
    {
        float tu = NdotV * 256.0f - 0.5f;
        float tv = rough * 256.0f - 0.5f;
        float x0f = floorf(tu);
        float y0f = floorf(tv);
        float fx = tu - x0f;
        if (x0f < 0.0f) fx = 0.0f;
        float fy = tv - y0f;
        if (y0f < 0.0f) fy = 0.0f;
        int x0 = (int)fminf(fmaxf(x0f, 0.0f), 255.0f);
        int y0 = (int)fminf(fmaxf(y0f, 0.0f), 255.0f);
        uint4 e = __ldg(g_fgq + y0 * 256 + x0);
        float2 c00 = __half22float2(*reinterpret_cast<const __half2*>(&e.x));
        float2 c01 = __half22float2(*reinterpret_cast<const __half2*>(&e.y));
        float2 c10 = __half22float2(*reinterpret_cast<const __half2*>(&e.z));
        float2 c11 = __half22float2(*reinterpret_cast<const __half2*>(&e.w));
        float a0 = c00.x + fx * (c01.x - c00.x);
        float b0 = c00.y + fx * (c01.y - c00.y);
        float a1 = c10.x + fx * (c11.x - c10.x);
        float b1 = c10.y + fx * (c11.y - c10.y);
        fg0 = a0 + fy * (a1 - a0);
        fg1 = b0 + fy * (b1 - b0);
    }

    // mip
    float mip;
    {
        const float L = (float)N_MIPS;
        float lo = (fminf(fmaxf(rough, MIN_ROUGHNESS), MAX_ROUGHNESS) - MIN_ROUGHNESS)
                   * ((L - 2.0f) / (MAX_ROUGHNESS - MIN_ROUGHNESS));
        float hi = (fminf(fmaxf(rough, MAX_ROUGHNESS), 1.0f) - MAX_ROUGHNESS)
                   * (1.0f / (1.0f - MAX_ROUGHNESS)) + (L - 2.0f);
        mip = (rough < MAX_ROUGHNESS) ? lo : hi;
        mip = fminf(fmaxf(mip, 0.0f), L - 1.0f);
    }

    int sface; float su, sv;
    cube_face_uv(rx, ry, rz, sface, su, sv);

    int l0 = (int)floorf(mip);
    if (l0 > N_MIPS - 1) l0 = N_MIPS - 1;
    float f = mip - (float)l0;
    int l1 = l0 + 1;
    if (l1 > N_MIPS - 1) l1 = N_MIPS - 1;

    // s1 always in the quad array (l1 >= 1); one LDG.128.
    float3x s1 = cube_bilinear_quad(g_specq + PAIR_OFF[l1 - 1], 512 >> l1,
                                    sface, su, sv);
    // s0: raw fp32 mip0 if l0==0 (~18.5% of pixels), else one quad load.
    float3x s0;
    if (l0 == 0) {
        s0 = cube_bilinear_raw(spec0, sface, su, sv);
    } else {
        s0 = cube_bilinear_quad(g_specq + PAIR_OFF[l0 - 1], 512 >> l0,
                                sface, su, sv);
    }

    float spx = s0.x + f * (s1.x - s0.x);
    float spy = s0.y + f * (s1.y - s0.y);
    float spz = s0.z + f * (s1.z - s0.z);

    float refx = sax * fg0 + fg1;
    float refy = say * fg0 + fg1;
    float refz = saz * fg0 + fg1;

    float cx = fminf(fmaxf(spx * refx + dlx, 0.0f), 1.0f);
    float cy = fminf(fmaxf(spy * refy + dly, 0.0f), 1.0f);
    float cz = fminf(fmaxf(spz * refz + dlz, 0.0f), 1.0f);

    __stcs(out + i * 3 + 0, linear2srgb(cx));
    __stcs(out + i * 3 + 1, linear2srgb(cy));
    __stcs(out + i * 3 + 2, linear2srgb(cz));
}

extern "C" void kernel_launch(void* const* d_in, const int* in_sizes, int n_in,
                              void* d_out, int out_size) {
    const float* gb_pos    = (const float*)d_in[0];
    const float* gb_normal = (const float*)d_in[1];
    const float* basecolor = (const float*)d_in[2];
    const float* metallic  = (const float*)d_in[3];
    const float* roughness = (const float*)d_in[4];
    const float* view_pos  = (const float*)d_in[5];
    const float* diffuse   = (const float*)d_in[6];
    const float* fg_lut    = (const float*)d_in[7];

    SpecTable specs;
    specs.p[0] = (const float*)d_in[8];
    specs.p[1] = (const float*)d_in[9];
    specs.p[2] = (const float*)d_in[10];
    specs.p[3] = (const float*)d_in[11];
    specs.p[4] = (const float*)d_in[12];
    specs.p[5] = (const float*)d_in[13];

    float* out = (float*)d_out;
    int n = in_sizes[0] / 3;

    // Pass 1: build quad records (mips 1..5 rgb9e5 + diffuse rgb9e5 + fg fp16)
    {
        int records = PAIR_TOTAL_TEXELS + DIFF_TEXELS + FG_TEXELS;
        int threads = 256;
        int blocks = (records + threads - 1) / threads;
        repack_kernel<<<blocks, threads>>>(specs, diffuse, fg_lut);
    }

    // Pass 2: shade, 1 px/thread at 6 blocks/SM
    {
        int threads = 256;
        int blocks = (n + threads - 1) / threads;
        envlight_kernel1<<<blocks, threads>>>(gb_pos, gb_normal, basecolor, metallic,
                                              roughness, view_pos, specs.p[0], out, n);
    }
}

// round 14
// speedup vs baseline: 1.1262x; 1.1262x over previous
#include <cuda_runtime.h>
#include <cuda_fp16.h>
#include <math.h>

#define MIN_ROUGHNESS 0.08f
#define MAX_ROUGHNESS 0.5f
#define N_MIPS 6

// Quad-record arrays: record at (x,y) holds the 2x2 bilinear footprint
// {(x,y),(x+1,y),(x,y+1),(x+1,y+1)}, neighbors clamped at face edges.
// Spec/diffuse texels are RGB9E5 (4B); FG is fp16 (fg0,fg1).
#define PAIR_TOTAL_TEXELS 523776   // mips 1..5
#define DIFF_TEXELS 1536
#define FG_TEXELS 65536

__constant__ int PAIR_OFF[6] = {0, 393216, 491520, 516096, 522240, 523776};

__device__ uint4 g_specq[PAIR_TOTAL_TEXELS];  // rgb9e5 quads (8.4 MB)
__device__ uint4 g_diffq[DIFF_TEXELS];        // rgb9e5 quads (24 KB)
__device__ uint4 g_fgq[FG_TEXELS];            // fp16 quads (1 MB)

struct SpecTable {
    const float* p[N_MIPS];
};

struct float3x { float x, y, z; };

// ---------------------------------------------------------------------------
// RGB9E5 encode (bit-math, no frexpf/exp2f)
// ---------------------------------------------------------------------------
__device__ __forceinline__ unsigned int enc_rgb9e5(float r, float g, float b) {
    r = fmaxf(r, 0.0f); g = fmaxf(g, 0.0f); b = fmaxf(b, 0.0f);
    float maxc = fmaxf(r, fmaxf(g, b));
    if (maxc < 1e-12f) return 0u;
    int e = (__float_as_int(maxc) >> 23) - 126;   // maxc in [0.5,1)*2^e
    if (e < -15) e = -15;
    if (e > 15)  e = 15;
    float scale = __int_as_float((136 - e) << 23);  // 2^(9-e)
    int mr = __float2int_rn(r * scale); if (mr > 511) mr = 511;
    int mg = __float2int_rn(g * scale); if (mg > 511) mg = 511;
    int mb = __float2int_rn(b * scale); if (mb > 511) mb = 511;
    return (unsigned int)mr | ((unsigned int)mg << 9) |
           ((unsigned int)mb << 18) | ((unsigned int)(e + 16) << 27);
}

// Exact magic-number decode: val = 2^(e+14)*(1+m/2^23) - 2^(e+14) = m*2^(e-9)
__device__ __forceinline__ float3x dec_rgb9e5(unsigned int v) {
    unsigned int eb = ((v >> 27) + 125u) << 23;
    float base = __int_as_float((int)eb);
    float3x c;
    c.x = __int_as_float((int)(eb | (v & 0x1FFu))) - base;
    c.y = __int_as_float((int)(eb | ((v >> 9) & 0x1FFu))) - base;
    c.z = __int_as_float((int)(eb | ((v >> 18) & 0x1FFu))) - base;
    return c;
}

// ---------------------------------------------------------------------------
// Repack pass. Spec: one thread = 4 consecutive records in one row (chunked:
// encode 5 texels per row once, share across records). Diffuse/FG: 1/thread.
// ---------------------------------------------------------------------------
#define SPEC_CHUNKS (PAIR_TOTAL_TEXELS / 4)   // 130944

// Read texels x..x+4 of one row into enc[5] (x multiple of 4, x+3 <= R-1).
__device__ __forceinline__ void encode_row5(const float* __restrict__ rowp,
                                            int x, int R,
                                            unsigned int enc[5]) {
    const float4* p4 = (const float4*)rowp;   // rowp points at texel x (12B-aligned, mult of 16B: see launch math)
    float4 A = __ldg(p4 + 0);
    float4 B = __ldg(p4 + 1);
    float4 C = __ldg(p4 + 2);
    float f[15];
    f[0] = A.x; f[1] = A.y; f[2]  = A.z; f[3]  = A.w;
    f[4] = B.x; f[5] = B.y; f[6]  = B.z; f[7]  = B.w;
    f[8] = C.x; f[9] = C.y; f[10] = C.z; f[11] = C.w;
    enc[0] = enc_rgb9e5(f[0], f[1], f[2]);
    enc[1] = enc_rgb9e5(f[3], f[4], f[5]);
    enc[2] = enc_rgb9e5(f[6], f[7], f[8]);
    enc[3] = enc_rgb9e5(f[9], f[10], f[11]);
    if (x + 4 < R) {
        f[12] = __ldg(rowp + 12);
        f[13] = __ldg(rowp + 13);
        f[14] = __ldg(rowp + 14);
        enc[4] = enc_rgb9e5(f[12], f[13], f[14]);
    } else {
        enc[4] = enc[3];
    }
}

__global__ void __launch_bounds__(256)
repack_kernel(SpecTable specs, const float* __restrict__ diffuse,
              const float* __restrict__ fg_lut) {
    const int NS = SPEC_CHUNKS;                 // spec chunk threads
    const int ND = NS + DIFF_TEXELS;
    const int NF = ND + FG_TEXELS;
    int q = blockIdx.x * blockDim.x + threadIdx.x;
    if (q >= NF) return;

    if (q < NS) {
        int t = q * 4;                           // first record index
        int lvl = 1;
        if (t >= 393216) lvl = 2;
        if (t >= 491520) lvl = 3;
        if (t >= 516096) lvl = 4;
        if (t >= 522240) lvl = 5;
        int local = t - PAIR_OFF[lvl - 1];
        int lr = 9 - lvl;
        int R = 1 << lr;
        int x = local & (R - 1);                 // multiple of 4
        int y = (local >> lr) & (R - 1);
        int face = local >> (2 * lr);
        int y1 = (y + 1 < R) ? (y + 1) : y;
        const float* base = specs.p[lvl] + (size_t)face * R * R * 3;

        unsigned int e0[5], e1[5];
        encode_row5(base + (y  * R + x) * 3, x, R, e0);
        encode_row5(base + (y1 * R + x) * 3, x, R, e1);

        #pragma unroll
        for (int i = 0; i < 4; i++) {
            uint4 o;
            o.x = e0[i]; o.y = e0[i + 1];
            o.z = e1[i]; o.w = e1[i + 1];
            g_specq[t + i] = o;
        }
    } else if (q < ND) {
        int local = q - NS;
        const int R = 16;
        int x = local & 15;
        int y = (local >> 4) & 15;
        int face = local >> 8;
        int x1 = (x + 1 < R) ? (x + 1) : x;
        int y1 = (y + 1 < R) ? (y + 1) : y;
        const float* base = diffuse + (size_t)face * 256 * 3;
        const float* t00 = base + (y  * R + x ) * 3;
        const float* t01 = base + (y  * R + x1) * 3;
        const float* t10 = base + (y1 * R + x ) * 3;
        const float* t11 = base + (y1 * R + x1) * 3;
        uint4 o;
        o.x = enc_rgb9e5(t00[0], t00[1], t00[2]);
        o.y = enc_rgb9e5(t01[0], t01[1], t01[2]);
        o.z = enc_rgb9e5(t10[0], t10[1], t10[2]);
        o.w = enc_rgb9e5(t11[0], t11[1], t11[2]);
        g_diffq[local] = o;
    } else {
        int local = q - ND;
        int x = local & 255;
        int y = local >> 8;
        int x1 = (x + 1 < 256) ? (x + 1) : x;
        int y1 = (y + 1 < 256) ? (y + 1) : y;
        const float2* fg = (const float2*)fg_lut;
        float2 c00 = __ldg(fg + y  * 256 + x);
        float2 c01 = __ldg(fg + y  * 256 + x1);
        float2 c10 = __ldg(fg + y1 * 256 + x);
        float2 c11 = __ldg(fg + y1 * 256 + x1);
        __half2 h00 = __floats2half2_rn(c00.x, c00.y);
        __half2 h01 = __floats2half2_rn(c01.x, c01.y);
        __half2 h10 = __floats2half2_rn(c10.x, c10.y);
        __half2 h11 = __floats2half2_rn(c11.x, c11.y);
        uint4 o;
        o.x = *reinterpret_cast<unsigned int*>(&h00);
        o.y = *reinterpret_cast<unsigned int*>(&h01);
        o.z = *reinterpret_cast<unsigned int*>(&h10);
        o.w = *reinterpret_cast<unsigned int*>(&h11);
        g_fgq[local] = o;
    }
}

// ---------------------------------------------------------------------------
// Main shading kernel
// ---------------------------------------------------------------------------
__device__ __forceinline__ void cube_face_uv(float x, float y, float z,
                                             int& face, float& u, float& v) {
    float ax = fabsf(x), ay = fabsf(y), az = fabsf(z);
    bool is_x = (ax >= ay) && (ax >= az);
    bool is_y = (!is_x) && (ay >= az);
    face = is_x ? (x >= 0.0f ? 0 : 1)
                : (is_y ? (y >= 0.0f ? 2 : 3)
                        : (z >= 0.0f ? 4 : 5));
    float ma = fmaxf(is_x ? ax : (is_y ? ay : az), 1e-20f);
    float un = (face == 0) ? -z : (face == 1) ? z : (face == 5) ? -x : x;
    float vn = (face == 2) ? z : (face == 3) ? -z : -y;
    float inv = __fdividef(1.0f, ma);
    u = un * inv;
    v = vn * inv;
}

// Quad-record bilinear: ONE LDG.128 per sample.
__device__ __forceinline__ float3x cube_bilinear_quad(const uint4* __restrict__ tex,
                                                      int R, int face,
                                                      float u, float v) {
    float Rf = (float)R;
    float tu = fmaf(u, 0.5f * Rf, 0.5f * Rf - 0.5f);
    float tv = fmaf(v, 0.5f * Rf, 0.5f * Rf - 0.5f);
    float x0f = floorf(tu);
    float y0f = floorf(tv);
    float fx = tu - x0f;
    if (x0f < 0.0f) fx = 0.0f;
    float fy = tv - y0f;
    if (y0f < 0.0f) fy = 0.0f;
    int x0 = (int)fminf(fmaxf(x0f, 0.0f), Rf - 1.0f);
    int y0 = (int)fminf(fmaxf(y0f, 0.0f), Rf - 1.0f);

    uint4 e = __ldg(tex + face * R * R + y0 * R + x0);
    float3x c00 = dec_rgb9e5(e.x);
    float3x c01 = dec_rgb9e5(e.y);
    float3x c10 = dec_rgb9e5(e.z);
    float3x c11 = dec_rgb9e5(e.w);

    float r0 = c00.x + fx * (c01.x - c00.x);
    float g0 = c00.y + fx * (c01.y - c00.y);
    float b0 = c00.z + fx * (c01.z - c00.z);
    float r1 = c10.x + fx * (c11.x - c10.x);
    float g1 = c10.y + fx * (c11.y - c10.y);
    float b1 = c10.z + fx * (c11.z - c10.z);

    float3x r;
    r.x = r0 + fy * (r1 - r0);
    r.y = g0 + fy * (g1 - g0);
    r.z = b0 + fy * (b1 - b0);
    return r;
}

// Raw fp32 RGB bilinear on the original mip-0 buffer (exact).
__device__ __forceinline__ float3x cube_bilinear_raw(const float* __restrict__ tex,
                                                     int face, float u, float v) {
    const float Rf = 512.0f;
    float tu = fmaf(u, 0.5f * Rf, 0.5f * Rf - 0.5f);
    float tv = fmaf(v, 0.5f * Rf, 0.5f * Rf - 0.5f);
    float x0f = floorf(tu);
    float y0f = floorf(tv);
    float fx = tu - x0f;
    float fy = tv - y0f;
    int x0 = (int)fminf(fmaxf(x0f, 0.0f), Rf - 1.0f);
    int x1 = (int)fminf(fmaxf(x0f + 1.0f, 0.0f), Rf - 1.0f);
    int y0 = (int)fminf(fmaxf(y0f, 0.0f), Rf - 1.0f);
    int y1 = (int)fminf(fmaxf(y0f + 1.0f, 0.0f), Rf - 1.0f);

    int baseF = face * 512 * 512;
    int i00 = (baseF + y0 * 512 + x0) * 3;
    int i01 = (baseF + y0 * 512 + x1) * 3;
    int i10 = (baseF + y1 * 512 + x0) * 3;
    int i11 = (baseF + y1 * 512 + x1) * 3;

    float w00 = (1.0f - fx) * (1.0f - fy);
    float w01 = fx * (1.0f - fy);
    float w10 = (1.0f - fx) * fy;
    float w11 = fx * fy;

    float3x r;
    r.x = __ldg(tex + i00 + 0) * w00 + __ldg(tex + i01 + 0) * w01 +
          __ldg(tex + i10 + 0) * w10 + __ldg(tex + i11 + 0) * w11;
    r.y = __ldg(tex + i00 + 1) * w00 + __ldg(tex + i01 + 1) * w01 +
          __ldg(tex + i10 + 1) * w10 + __ldg(tex + i11 + 1) * w11;
    r.z = __ldg(tex + i00 + 2) * w00 + __ldg(tex + i01 + 2) * w01 +
          __ldg(tex + i10 + 2) * w10 + __ldg(tex + i11 + 2) * w11;
    return r;
}

__device__ __forceinline__ float linear2srgb(float x) {
    float l = __log2f(x);
    float y = l * (1.0f / 2.4f);
    float fl = floorf(y);
    float t = y - fl;
    float p = fmaf(t,
              fmaf(t,
              fmaf(t,
              fmaf(t,
              fmaf(t, 0.0013333558f, 0.0096181291f),
                       0.0555041087f),
                       0.2402265070f),
                       0.6931471806f),
                       1.0f);
    int e = (int)fl;
    float r = __int_as_float(__float_as_int(p) + (e << 23));
    float hi = fmaf(1.055f, r, -0.055f);
    return (x > 0.0031308f) ? hi : 12.92f * x;
}

__global__ void __launch_bounds__(256, 6)
envlight_kernel1(const float* __restrict__ gb_pos,
                 const float* __restrict__ gb_normal,
                 const float* __restrict__ basecolor,
                 const float* __restrict__ metallic,
                 const float* __restrict__ roughness,
                 const float* __restrict__ view_pos,
                 const float* __restrict__ spec0,
                 float* __restrict__ out,
                 int n) {
    int i = blockIdx.x * blockDim.x + threadIdx.x;
    if (i >= n) return;

    float vx = __ldg(view_pos + 0);
    float vy = __ldg(view_pos + 1);
    float vz = __ldg(view_pos + 2);

    float px = __ldcs(gb_pos + i * 3 + 0);
    float py = __ldcs(gb_pos + i * 3 + 1);
    float pz = __ldcs(gb_pos + i * 3 + 2);
    float nx = __ldcs(gb_normal + i * 3 + 0);
    float ny = __ldcs(gb_normal + i * 3 + 1);
    float nz = __ldcs(gb_normal + i * 3 + 2);
    float bcx = __ldcs(basecolor + i * 3 + 0);
    float bcy = __ldcs(basecolor + i * 3 + 1);
    float bcz = __ldcs(basecolor + i * 3 + 2);
    float met = __ldcs(metallic + i);
    float rough = __ldcs(roughness + i);

    // wo left unnormalized; only NdotV needs the normalization factor.
    float wx = vx - px, wy = vy - py, wz = vz - pz;
    float wlen2 = fmaxf(wx * wx + wy * wy + wz * wz, 1e-20f);
    float winv = rsqrtf(wlen2);

    float om = 1.0f - met;
    float dax = om * bcx, day = om * bcy, daz = om * bcz;
    float sax = 0.04f * om + met * bcx;
    float say = 0.04f * om + met * bcy;
    float saz = 0.04f * om + met * bcz;

    float d_un = wx * nx + wy * ny + wz * nz;
    float rx = 2.0f * d_un * nx - wx;
    float ry = 2.0f * d_un * ny - wy;
    float rz = 2.0f * d_un * nz - wz;

    // ambient from diffuse cubemap (one quad load)
    int dface; float du, dv;
    cube_face_uv(nx, ny, nz, dface, du, dv);
    float3x ambient = cube_bilinear_quad(g_diffq, 16, dface, du, dv);

    float dlx = ambient.x * dax;
    float dly = ambient.y * day;
    float dlz = ambient.z * daz;

    // FG LUT: one LDG.128 quad record (fp16)
    float NdotV = fmaxf(d_un * winv, 0.0001f);
    float fg0, fg1;
    {
        float tu = NdotV * 256.0f - 0.5f;
        float tv = rough * 256.0f - 0.5f;
        float x0f = floorf(tu);
        float y0f = floorf(tv);
        float fx = tu - x0f;
        if (x0f < 0.0f) fx = 0.0f;
        float fy = tv - y0f;
        if (y0f < 0.0f) fy = 0.0f;
        int x0 = (int)fminf(fmaxf(x0f, 0.0f), 255.0f);
        int y0 = (int)fminf(fmaxf(y0f, 0.0f), 255.0f);
        uint4 e = __ldg(g_fgq + y0 * 256 + x0);
        float2 c00 = __half22float2(*reinterpret_cast<const __half2*>(&e.x));
        float2 c01 = __half22float2(*reinterpret_cast<const __half2*>(&e.y));
        float2 c10 = __half22float2(*reinterpret_cast<const __half2*>(&e.z));
        float2 c11 = __half22float2(*reinterpret_cast<const __half2*>(&e.w));
        float a0 = c00.x + fx * (c01.x - c00.x);
        float b0 = c00.y + fx * (c01.y - c00.y);
        float a1 = c10.x + fx * (c11.x - c10.x);
        float b1 = c10.y + fx * (c11.y - c10.y);
        fg0 = a0 + fy * (a1 - a0);
        fg1 = b0 + fy * (b1 - b0);
    }

    // mip
    float mip;
    {
        const float L = (float)N_MIPS;
        float lo = (fminf(fmaxf(rough, MIN_ROUGHNESS), MAX_ROUGHNESS) - MIN_ROUGHNESS)
                   * ((L - 2.0f) / (MAX_ROUGHNESS - MIN_ROUGHNESS));
        float hi = (fminf(fmaxf(rough, MAX_ROUGHNESS), 1.0f) - MAX_ROUGHNESS)
                   * (1.0f / (1.0f - MAX_ROUGHNESS)) + (L - 2.0f);
        mip = (rough < MAX_ROUGHNESS) ? lo : hi;
        mip = fminf(fmaxf(mip, 0.0f), L - 1.0f);
    }

    int sface; float su, sv;
    cube_face_uv(rx, ry, rz, sface, su, sv);

    int l0 = (int)floorf(mip);
    if (l0 > N_MIPS - 1) l0 = N_MIPS - 1;
    float f = mip - (float)l0;
    int l1 = l0 + 1;
    if (l1 > N_MIPS - 1) l1 = N_MIPS - 1;

    // s1 always in the quad array (l1 >= 1); one LDG.128.
    float3x s1 = cube_bilinear_quad(g_specq + PAIR_OFF[l1 - 1], 512 >> l1,
                                    sface, su, sv);
    // s0: raw fp32 mip0 if l0==0 (~18.5% of pixels), else one quad load.
    float3x s0;
    if (l0 == 0) {
        s0 = cube_bilinear_raw(spec0, sface, su, sv);
    } else {
        s0 = cube_bilinear_quad(g_specq + PAIR_OFF[l0 - 1], 512 >> l0,
                                sface, su, sv);
    }

    float spx = s0.x + f * (s1.x - s0.x);
    float spy = s0.y + f * (s1.y - s0.y);
    float spz = s0.z + f * (s1.z - s0.z);

    float refx = sax * fg0 + fg1;
    float refy = say * fg0 + fg1;
    float refz = saz * fg0 + fg1;

    float cx = fminf(fmaxf(spx * refx + dlx, 0.0f), 1.0f);
    float cy = fminf(fmaxf(spy * refy + dly, 0.0f), 1.0f);
    float cz = fminf(fmaxf(spz * refz + dlz, 0.0f), 1.0f);

    __stcs(out + i * 3 + 0, linear2srgb(cx));
    __stcs(out + i * 3 + 1, linear2srgb(cy));
    __stcs(out + i * 3 + 2, linear2srgb(cz));
}

extern "C" void kernel_launch(void* const* d_in, const int* in_sizes, int n_in,
                              void* d_out, int out_size) {
    const float* gb_pos    = (const float*)d_in[0];
    const float* gb_normal = (const float*)d_in[1];
    const float* basecolor = (const float*)d_in[2];
    const float* metallic  = (const float*)d_in[3];
    const float* roughness = (const float*)d_in[4];
    const float* view_pos  = (const float*)d_in[5];
    const float* diffuse   = (const float*)d_in[6];
    const float* fg_lut    = (const float*)d_in[7];

    SpecTable specs;
    specs.p[0] = (const float*)d_in[8];
    specs.p[1] = (const float*)d_in[9];
    specs.p[2] = (const float*)d_in[10];
    specs.p[3] = (const float*)d_in[11];
    specs.p[4] = (const float*)d_in[12];
    specs.p[5] = (const float*)d_in[13];

    float* out = (float*)d_out;
    int n = in_sizes[0] / 3;

    // Pass 1: build quad records (spec chunked; diffuse/fg 1 per thread)
    {
        int total = SPEC_CHUNKS + DIFF_TEXELS + FG_TEXELS;
        int threads = 256;
        int blocks = (total + threads - 1) / threads;
        repack_kernel<<<blocks, threads>>>(specs, diffuse, fg_lut);
    }

    // Pass 2: shade, 1 px/thread at 6 blocks/SM
    {
        int threads = 256;
        int blocks = (n + threads - 1) / threads;
        envlight_kernel1<<<blocks, threads>>>(gb_pos, gb_normal, basecolor, metallic,
                                              roughness, view_pos, specs.p[0], out, n);
    }
}

// round 15
// speedup vs baseline: 1.1761x; 1.0443x over previous
#include <cuda_runtime.h>
#include <cuda_fp16.h>
#include <math.h>

#define MIN_ROUGHNESS 0.08f
#define MAX_ROUGHNESS 0.5f
#define N_MIPS 6

// Quad-record arrays: record at (x,y) holds the 2x2 bilinear footprint,
// neighbors clamped at face edges. Spec/diffuse RGB9E5; FG fp16.
#define PAIR_TOTAL_TEXELS 523776   // mips 1..5
#define DIFF_TEXELS 1536
#define FG_TEXELS 65536

__constant__ int PAIR_OFF[6] = {0, 393216, 491520, 516096, 522240, 523776};

__device__ uint4 g_specq[PAIR_TOTAL_TEXELS];
__device__ uint4 g_diffq[DIFF_TEXELS];
__device__ uint4 g_fgq[FG_TEXELS];

struct SpecTable {
    const float* p[N_MIPS];
};

struct float3x { float x, y, z; };

// ---------------------------------------------------------------------------
// RGB9E5 encode / exact magic-number decode
// ---------------------------------------------------------------------------
__device__ __forceinline__ unsigned int enc_rgb9e5(float r, float g, float b) {
    r = fmaxf(r, 0.0f); g = fmaxf(g, 0.0f); b = fmaxf(b, 0.0f);
    float maxc = fmaxf(r, fmaxf(g, b));
    if (maxc < 1e-12f) return 0u;
    int e = (__float_as_int(maxc) >> 23) - 126;
    if (e < -15) e = -15;
    if (e > 15)  e = 15;
    float scale = __int_as_float((136 - e) << 23);  // 2^(9-e)
    int mr = __float2int_rn(r * scale); if (mr > 511) mr = 511;
    int mg = __float2int_rn(g * scale); if (mg > 511) mg = 511;
    int mb = __float2int_rn(b * scale); if (mb > 511) mb = 511;
    return (unsigned int)mr | ((unsigned int)mg << 9) |
           ((unsigned int)mb << 18) | ((unsigned int)(e + 16) << 27);
}

__device__ __forceinline__ float3x dec_rgb9e5(unsigned int v) {
    unsigned int eb = ((v >> 27) + 125u) << 23;
    float base = __int_as_float((int)eb);
    float3x c;
    c.x = __int_as_float((int)(eb | (v & 0x1FFu))) - base;
    c.y = __int_as_float((int)(eb | ((v >> 9) & 0x1FFu))) - base;
    c.z = __int_as_float((int)(eb | ((v >> 18) & 0x1FFu))) - base;
    return c;
}

// ---------------------------------------------------------------------------
// Repack pass. Spec: 4 records/thread (row-shared encodes). FG: 4 records/
// thread. Diffuse: 1 record/thread.
// ---------------------------------------------------------------------------
#define SPEC_CHUNKS (PAIR_TOTAL_TEXELS / 4)   // 130944
#define FG_CHUNKS   (FG_TEXELS / 4)           // 16384

__device__ __forceinline__ void encode_row5(const float* __restrict__ rowp,
                                            int x, int R,
                                            unsigned int enc[5]) {
    const float4* p4 = (const float4*)rowp;
    float4 A = __ldg(p4 + 0);
    float4 B = __ldg(p4 + 1);
    float4 C = __ldg(p4 + 2);
    enc[0] = enc_rgb9e5(A.x, A.y, A.z);
    enc[1] = enc_rgb9e5(A.w, B.x, B.y);
    enc[2] = enc_rgb9e5(B.z, B.w, C.x);
    enc[3] = enc_rgb9e5(C.y, C.z, C.w);
    if (x + 4 < R) {
        float r = __ldg(rowp + 12);
        float g = __ldg(rowp + 13);
        float b = __ldg(rowp + 14);
        enc[4] = enc_rgb9e5(r, g, b);
    } else {
        enc[4] = enc[3];
    }
}

__global__ void __launch_bounds__(256)
repack_kernel(SpecTable specs, const float* __restrict__ diffuse,
              const float* __restrict__ fg_lut) {
    const int NS = SPEC_CHUNKS;
    const int ND = NS + DIFF_TEXELS;
    const int NF = ND + FG_CHUNKS;
    int q = blockIdx.x * blockDim.x + threadIdx.x;
    if (q >= NF) return;

    if (q < NS) {
        int t = q * 4;
        int lvl = 1;
        if (t >= 393216) lvl = 2;
        if (t >= 491520) lvl = 3;
        if (t >= 516096) lvl = 4;
        if (t >= 522240) lvl = 5;
        int local = t - PAIR_OFF[lvl - 1];
        int lr = 9 - lvl;
        int R = 1 << lr;
        int x = local & (R - 1);
        int y = (local >> lr) & (R - 1);
        int face = local >> (2 * lr);
        int y1 = (y + 1 < R) ? (y + 1) : y;
        const float* base = specs.p[lvl] + (size_t)face * R * R * 3;

        unsigned int e0[5], e1[5];
        encode_row5(base + (y  * R + x) * 3, x, R, e0);
        encode_row5(base + (y1 * R + x) * 3, x, R, e1);

        #pragma unroll
        for (int i = 0; i < 4; i++) {
            uint4 o;
            o.x = e0[i]; o.y = e0[i + 1];
            o.z = e1[i]; o.w = e1[i + 1];
            g_specq[t + i] = o;
        }
    } else if (q < ND) {
        int local = q - NS;
        const int R = 16;
        int x = local & 15;
        int y = (local >> 4) & 15;
        int face = local >> 8;
        int x1 = (x + 1 < R) ? (x + 1) : x;
        int y1 = (y + 1 < R) ? (y + 1) : y;
        const float* base = diffuse + (size_t)face * 256 * 3;
        const float* t00 = base + (y  * R + x ) * 3;
        const float* t01 = base + (y  * R + x1) * 3;
        const float* t10 = base + (y1 * R + x ) * 3;
        const float* t11 = base + (y1 * R + x1) * 3;
        uint4 o;
        o.x = enc_rgb9e5(t00[0], t00[1], t00[2]);
        o.y = enc_rgb9e5(t01[0], t01[1], t01[2]);
        o.z = enc_rgb9e5(t10[0], t10[1], t10[2]);
        o.w = enc_rgb9e5(t11[0], t11[1], t11[2]);
        g_diffq[local] = o;
    } else {
        // FG: 4 records per thread, row-shared loads.
        int t = (q - ND) * 4;
        int y = t >> 8;
        int x = t & 255;                       // multiple of 4
        int y1 = (y + 1 < 256) ? (y + 1) : y;
        const float2* fg = (const float2*)fg_lut;

        unsigned int h0[5], h1[5];
        {
            const float4* p = (const float4*)(fg + y * 256 + x);
            float4 a = __ldg(p + 0);
            float4 b = __ldg(p + 1);
            __half2 t0 = __floats2half2_rn(a.x, a.y);
            __half2 t1 = __floats2half2_rn(a.z, a.w);
            __half2 t2 = __floats2half2_rn(b.x, b.y);
            __half2 t3 = __floats2half2_rn(b.z, b.w);
            h0[0] = *reinterpret_cast<unsigned int*>(&t0);
            h0[1] = *reinterpret_cast<unsigned int*>(&t1);
            h0[2] = *reinterpret_cast<unsigned int*>(&t2);
            h0[3] = *reinterpret_cast<unsigned int*>(&t3);
            if (x + 4 < 256) {
                float2 e = __ldg(fg + y * 256 + x + 4);
                __half2 t4 = __floats2half2_rn(e.x, e.y);
                h0[4] = *reinterpret_cast<unsigned int*>(&t4);
            } else h0[4] = h0[3];
        }
        {
            const float4* p = (const float4*)(fg + y1 * 256 + x);
            float4 a = __ldg(p + 0);
            float4 b = __ldg(p + 1);
            __half2 t0 = __floats2half2_rn(a.x, a.y);
            __half2 t1 = __floats2half2_rn(a.z, a.w);
            __half2 t2 = __floats2half2_rn(b.x, b.y);
            __half2 t3 = __floats2half2_rn(b.z, b.w);
            h1[0] = *reinterpret_cast<unsigned int*>(&t0);
            h1[1] = *reinterpret_cast<unsigned int*>(&t1);
            h1[2] = *reinterpret_cast<unsigned int*>(&t2);
            h1[3] = *reinterpret_cast<unsigned int*>(&t3);
            if (x + 4 < 256) {
                float2 e = __ldg(fg + y1 * 256 + x + 4);
                __half2 t4 = __floats2half2_rn(e.x, e.y);
                h1[4] = *reinterpret_cast<unsigned int*>(&t4);
            } else h1[4] = h1[3];
        }
        #pragma unroll
        for (int i = 0; i < 4; i++) {
            uint4 o;
            o.x = h0[i]; o.y = h0[i + 1];
            o.z = h1[i]; o.w = h1[i + 1];
            g_fgq[t + i] = o;
        }
    }
}

// ---------------------------------------------------------------------------
// Main shading kernel
// ---------------------------------------------------------------------------
__device__ __forceinline__ void cube_face_uv(float x, float y, float z,
                                             int& face, float& u, float& v) {
    float ax = fabsf(x), ay = fabsf(y), az = fabsf(z);
    bool is_x = (ax >= ay) && (ax >= az);
    bool is_y = (!is_x) && (ay >= az);
    face = is_x ? (x >= 0.0f ? 0 : 1)
                : (is_y ? (y >= 0.0f ? 2 : 3)
                        : (z >= 0.0f ? 4 : 5));
    float ma = fmaxf(is_x ? ax : (is_y ? ay : az), 1e-20f);
    float un = (face == 0) ? -z : (face == 1) ? z : (face == 5) ? -x : x;
    float vn = (face == 2) ? z : (face == 3) ? -z : -y;
    float inv = __fdividef(1.0f, ma);
    u = un * inv;
    v = vn * inv;
}

// Quad bilinear, lr = log2(R). Lower clamp only (records self-duplicate at
// the upper edge; fmaxf(tu,0) reproduces the reference's left-edge blend).
__device__ __forceinline__ float3x cube_bilinear_quad(const uint4* __restrict__ tex,
                                                      int lr, int face,
                                                      float u, float v) {
    float hR = __int_as_float((lr + 126) << 23);   // R/2 = 2^(lr-1)
    float tu = fmaxf(fmaf(u, hR, hR - 0.5f), 0.0f);
    float tv = fmaxf(fmaf(v, hR, hR - 0.5f), 0.0f);
    float x0f = floorf(tu);
    float y0f = floorf(tv);
    float fx = tu - x0f;
    float fy = tv - y0f;
    int x0 = (int)x0f;
    int y0 = (int)y0f;

    uint4 e = __ldg(tex + (face << (2 * lr)) + (y0 << lr) + x0);
    float3x c00 = dec_rgb9e5(e.x);
    float3x c01 = dec_rgb9e5(e.y);
    float3x c10 = dec_rgb9e5(e.z);
    float3x c11 = dec_rgb9e5(e.w);

    float r0 = c00.x + fx * (c01.x - c00.x);
    float g0 = c00.y + fx * (c01.y - c00.y);
    float b0 = c00.z + fx * (c01.z - c00.z);
    float r1 = c10.x + fx * (c11.x - c10.x);
    float g1 = c10.y + fx * (c11.y - c10.y);
    float b1 = c10.z + fx * (c11.z - c10.z);

    float3x r;
    r.x = r0 + fy * (r1 - r0);
    r.y = g0 + fy * (g1 - g0);
    r.z = b0 + fy * (b1 - b0);
    return r;
}

// Raw fp32 RGB bilinear on mip0 (exact). Lower clamp via fmaxf; upper only
// for the +1 taps.
__device__ __forceinline__ float3x cube_bilinear_raw(const float* __restrict__ tex,
                                                     int face, float u, float v) {
    float tu = fmaxf(fmaf(u, 256.0f, 255.5f), 0.0f);
    float tv = fmaxf(fmaf(v, 256.0f, 255.5f), 0.0f);
    float x0f = floorf(tu);
    float y0f = floorf(tv);
    float fx = tu - x0f;
    float fy = tv - y0f;
    int x0 = (int)x0f;
    int y0 = (int)y0f;
    int x1 = min(x0 + 1, 511);
    int y1 = min(y0 + 1, 511);

    int baseF = face << 18;
    int i00 = (baseF + (y0 << 9) + x0) * 3;
    int i01 = (baseF + (y0 << 9) + x1) * 3;
    int i10 = (baseF + (y1 << 9) + x0) * 3;
    int i11 = (baseF + (y1 << 9) + x1) * 3;

    float w00 = (1.0f - fx) * (1.0f - fy);
    float w01 = fx * (1.0f - fy);
    float w10 = (1.0f - fx) * fy;
    float w11 = fx * fy;

    float3x r;
    r.x = __ldg(tex + i00 + 0) * w00 + __ldg(tex + i01 + 0) * w01 +
          __ldg(tex + i10 + 0) * w10 + __ldg(tex + i11 + 0) * w11;
    r.y = __ldg(tex + i00 + 1) * w00 + __ldg(tex + i01 + 1) * w01 +
          __ldg(tex + i10 + 1) * w10 + __ldg(tex + i11 + 1) * w11;
    r.z = __ldg(tex + i00 + 2) * w00 + __ldg(tex + i01 + 2) * w01 +
          __ldg(tex + i10 + 2) * w10 + __ldg(tex + i11 + 2) * w11;
    return r;
}

__device__ __forceinline__ float linear2srgb(float x) {
    float l = __log2f(x);
    float y = l * (1.0f / 2.4f);
    float fl = floorf(y);
    float t = y - fl;
    float p = fmaf(t,
              fmaf(t,
              fmaf(t,
              fmaf(t,
              fmaf(t, 0.0013333558f, 0.0096181291f),
                       0.0555041087f),
                       0.2402265070f),
                       0.6931471806f),
                       1.0f);
    int e = (int)fl;
    float r = __int_as_float(__float_as_int(p) + (e << 23));
    float hi = fmaf(1.055f, r, -0.055f);
    return (x > 0.0031308f) ? hi : 12.92f * x;
}

__global__ void __launch_bounds__(256, 6)
envlight_kernel1(const float* __restrict__ gb_pos,
                 const float* __restrict__ gb_normal,
                 const float* __restrict__ basecolor,
                 const float* __restrict__ metallic,
                 const float* __restrict__ roughness,
                 const float* __restrict__ view_pos,
                 const float* __restrict__ spec0,
                 float* __restrict__ out,
                 int n) {
    int i = blockIdx.x * blockDim.x + threadIdx.x;
    if (i >= n) return;

    float vx = __ldg(view_pos + 0);
    float vy = __ldg(view_pos + 1);
    float vz = __ldg(view_pos + 2);

    float px = __ldcs(gb_pos + i * 3 + 0);
    float py = __ldcs(gb_pos + i * 3 + 1);
    float pz = __ldcs(gb_pos + i * 3 + 2);
    float nx = __ldcs(gb_normal + i * 3 + 0);
    float ny = __ldcs(gb_normal + i * 3 + 1);
    float nz = __ldcs(gb_normal + i * 3 + 2);
    float bcx = __ldcs(basecolor + i * 3 + 0);
    float bcy = __ldcs(basecolor + i * 3 + 1);
    float bcz = __ldcs(basecolor + i * 3 + 2);
    float met = __ldcs(metallic + i);
    float rough = __ldcs(roughness + i);

    // wo left unnormalized; only NdotV needs the normalization factor.
    float wx = vx - px, wy = vy - py, wz = vz - pz;
    float wlen2 = fmaxf(wx * wx + wy * wy + wz * wz, 1e-20f);
    float winv = rsqrtf(wlen2);

    float om = 1.0f - met;
    float dax = om * bcx, day = om * bcy, daz = om * bcz;
    float sax = 0.04f * om + met * bcx;
    float say = 0.04f * om + met * bcy;
    float saz = 0.04f * om + met * bcz;

    float d_un = wx * nx + wy * ny + wz * nz;
    float rx = 2.0f * d_un * nx - wx;
    float ry = 2.0f * d_un * ny - wy;
    float rz = 2.0f * d_un * nz - wz;

    // ambient from diffuse cubemap (one quad load, lr=4)
    int dface; float du, dv;
    cube_face_uv(nx, ny, nz, dface, du, dv);
    float3x ambient = cube_bilinear_quad(g_diffq, 4, dface, du, dv);

    float dlx = ambient.x * dax;
    float dly = ambient.y * day;
    float dlz = ambient.z * daz;

    // FG LUT: one LDG.128 quad record (fp16)
    float NdotV = fmaxf(d_un * winv, 0.0001f);
    float fg0, fg1;
    {
        float tu = fmaxf(NdotV * 256.0f - 0.5f, 0.0f);
        float tv = fmaxf(rough * 256.0f - 0.5f, 0.0f);
        float x0f = floorf(tu);
        float y0f = floorf(tv);
        float fx = tu - x0f;
        float fy = tv - y0f;
        int x0 = (int)x0f;
        int y0 = (int)y0f;
        uint4 e = __ldg(g_fgq + (y0 << 8) + x0);
        float2 c00 = __half22float2(*reinterpret_cast<const __half2*>(&e.x));
        float2 c01 = __half22float2(*reinterpret_cast<const __half2*>(&e.y));
        float2 c10 = __half22float2(*reinterpret_cast<const __half2*>(&e.z));
        float2 c11 = __half22float2(*reinterpret_cast<const __half2*>(&e.w));
        float a0 = c00.x + fx * (c01.x - c00.x);
        float b0 = c00.y + fx * (c01.y - c00.y);
        float a1 = c10.x + fx * (c11.x - c10.x);
        float b1 = c10.y + fx * (c11.y - c10.y);
        fg0 = a0 + fy * (a1 - a0);
        fg1 = b0 + fy * (b1 - b0);
    }

    // mip
    float mip;
    {
        const float L = (float)N_MIPS;
        float lo = (fminf(fmaxf(rough, MIN_ROUGHNESS), MAX_ROUGHNESS) - MIN_ROUGHNESS)
                   * ((L - 2.0f) / (MAX_ROUGHNESS - MIN_ROUGHNESS));
        float hi = (fminf(fmaxf(rough, MAX_ROUGHNESS), 1.0f) - MAX_ROUGHNESS)
                   * (1.0f / (1.0f - MAX_ROUGHNESS)) + (L - 2.0f);
        mip = (rough < MAX_ROUGHNESS) ? lo : hi;
        mip = fminf(fmaxf(mip, 0.0f), L - 1.0f);
    }

    int sface; float su, sv;
    cube_face_uv(rx, ry, rz, sface, su, sv);

    int l0 = (int)floorf(mip);
    if (l0 > N_MIPS - 1) l0 = N_MIPS - 1;
    float f = mip - (float)l0;
    int l1 = l0 + 1;
    if (l1 > N_MIPS - 1) l1 = N_MIPS - 1;

    // s1 always in the quad array (l1 >= 1); one LDG.128.
    float3x s1 = cube_bilinear_quad(g_specq + PAIR_OFF[l1 - 1], 9 - l1,
                                    sface, su, sv);
    // s0: raw fp32 mip0 if l0==0 (~18.5% of pixels), else one quad load.
    float3x s0;
    if (l0 == 0) {
        s0 = cube_bilinear_raw(spec0, sface, su, sv);
    } else {
        s0 = cube_bilinear_quad(g_specq + PAIR_OFF[l0 - 1], 9 - l0,
                                sface, su, sv);
    }

    float spx = s0.x + f * (s1.x - s0.x);
    float spy = s0.y + f * (s1.y - s0.y);
    float spz = s0.z + f * (s1.z - s0.z);

    float refx = sax * fg0 + fg1;
    float refy = say * fg0 + fg1;
    float refz = saz * fg0 + fg1;

    float cx = fminf(fmaxf(spx * refx + dlx, 0.0f), 1.0f);
    float cy = fminf(fmaxf(spy * refy + dly, 0.0f), 1.0f);
    float cz = fminf(fmaxf(spz * refz + dlz, 0.0f), 1.0f);

    __stcs(out + i * 3 + 0, linear2srgb(cx));
    __stcs(out + i * 3 + 1, linear2srgb(cy));
    __stcs(out + i * 3 + 2, linear2srgb(cz));
}

extern "C" void kernel_launch(void* const* d_in, const int* in_sizes, int n_in,
                              void* d_out, int out_size) {
    const float* gb_pos    = (const float*)d_in[0];
    const float* gb_normal = (const float*)d_in[1];
    const float* basecolor = (const float*)d_in[2];
    const float* metallic  = (const float*)d_in[3];
    const float* roughness = (const float*)d_in[4];
    const float* view_pos  = (const float*)d_in[5];
    const float* diffuse   = (const float*)d_in[6];
    const float* fg_lut    = (const float*)d_in[7];

    SpecTable specs;
    specs.p[0] = (const float*)d_in[8];
    specs.p[1] = (const float*)d_in[9];
    specs.p[2] = (const float*)d_in[10];
    specs.p[3] = (const float*)d_in[11];
    specs.p[4] = (const float*)d_in[12];
    specs.p[5] = (const float*)d_in[13];

    float* out = (float*)d_out;
    int n = in_sizes[0] / 3;

    // Pass 1: build quad records
    {
        int total = SPEC_CHUNKS + DIFF_TEXELS + FG_CHUNKS;
        int threads = 256;
        int blocks = (total + threads - 1) / threads;
        repack_kernel<<<blocks, threads>>>(specs, diffuse, fg_lut);
    }

    // Pass 2: shade
    {
        int threads = 256;
        int blocks = (n + threads - 1) / threads;
        envlight_kernel1<<<blocks, threads>>>(gb_pos, gb_normal, basecolor, metallic,
                                              roughness, view_pos, specs.p[0], out, n);
    }
}